// round 12
// baseline (speedup 1.0000x reference)
#include <cuda_runtime.h>
#include <cuda_bf16.h>

// Problem constants: b=1, h=w=64, s=5, H=W=1024, ps=32, q=8
#define GRID_T   64
#define NTILES   (GRID_T * GRID_T)      // 4096
#define NSTROKE  5
#define IMG      1024
#define PLANE    (IMG * IMG)            // 1048576

__device__ __forceinline__ float tanh_(float x) {
    float r; asm("tanh.approx.f32 %0,%1;" : "=f"(r) : "f"(x)); return r;
}

// ---------------------------------------------------------------------------
// Single fused kernel. Block = one 16x16 padded-aligned cell, 64 threads
// (16x4), 4 pixels/thread (rows ty+{0,4,8,12}).
//
//   1. Warp 0 lanes 0..19 stage: inline prep (sigmoid/sincos), per-pass
//      counts exchanged via shfl, entries written to smem in REVERSED blend
//      order (=> front-to-back compositing). ONE __syncthreads total.
//   2. Front-to-back transmittance blend; u/v per pixel via independent FMA.
//   3. Canvas read AFTER the loop: out = acc + canvas*T.
//
// __launch_bounds__(64, 25) pins regs <= 40 (R11 showed occupancy collapse
// when register lifetimes crossed the main loop).
// ---------------------------------------------------------------------------
__global__ void __launch_bounds__(64, 25)
render_kernel(const float* __restrict__ param,
              const int*   __restrict__ decision,
              const float* __restrict__ canvas,
              float*       __restrict__ out) {
    __shared__ float4 sA[4 * NSTROKE];   // (C, S, U0', V0')  [scaled by 25]
    __shared__ float4 sB[4 * NSTROKE];   // (W, H, dS, dC)    [scaled by 25]
    __shared__ float4 sC[4 * NSTROKE];   // (cr, cg, cb, -)
    __shared__ int    sTot;

    const int a = blockIdx.y;            // padded cell row: Y in [16a, 16a+16)
    const int b = blockIdx.x;
    const int tx  = threadIdx.x;         // 0..15
    const int ty  = threadIdx.y;         // 0..3
    const int tid = ty * 16 + tx;

    // --- warp-synchronous staging (warp 0, lanes 0..19) ---
    if (tid < 32) {
        const int lane = tid;
        const int PR[4] = {0, 1, 1, 0};
        const int PC[4] = {0, 1, 0, 1};
        int p = 0, i = 0, r = 0, c = 0, t = 0;
        int dec[NSTROKE];
        #pragma unroll
        for (int j = 0; j < NSTROKE; j++) dec[j] = 0;

        if (lane < 4 * NSTROKE) {
            p = lane / NSTROKE; i = lane - p * NSTROKE;
            r = (((a - 1) & 1) == PR[p]) ? (a - 1) : a;
            c = (((b - 1) & 1) == PC[p]) ? (b - 1) : b;
            t = r * GRID_T + c;
            if (((unsigned)r < 64u) && ((unsigned)c < 64u)) {
                #pragma unroll
                for (int j = 0; j < NSTROKE; j++)
                    dec[j] = decision[t * NSTROKE + j];
            }
        }
        int cnt = 0;
        #pragma unroll
        for (int j = 0; j < NSTROKE; j++) cnt += (dec[j] != 0);

        const int c0 = __shfl_sync(0xffffffffu, cnt, 0);
        const int c1 = __shfl_sync(0xffffffffu, cnt, 5);
        const int c2 = __shfl_sync(0xffffffffu, cnt, 10);
        const int c3 = __shfl_sync(0xffffffffu, cnt, 15);
        const int tot = c0 + c1 + c2 + c3;
        if (lane == 0) sTot = tot;

        if (lane < 4 * NSTROKE && dec[i] != 0) {
            int pos = 0;
            #pragma unroll
            for (int j = 0; j < NSTROKE; j++) pos += (j < i) && (dec[j] != 0);
            int base = ((p > 0) ? c0 : 0) + ((p > 1) ? c1 : 0) + ((p > 2) ? c2 : 0);
            int e = tot - 1 - (base + pos);      // reversed => front-to-back

            const float* q = param + (size_t)(t * NSTROKE + i) * 12;
            float p8[8];
            #pragma unroll
            for (int k = 0; k < 8; k++)
                p8[k] = __fdividef(1.0f, 1.0f + __expf(-q[k]));  // sigmoid

            float x0 = p8[0], yc = p8[1];
            float W = 12.5f * fmaxf(p8[2], 0.01f);   // 25 * (wd/2)
            float H = 12.5f * fmaxf(p8[3], 0.01f);
            float th = p8[4] * 3.14159265358979323846f;
            float st, ct;
            __sincosf(th, &st, &ct);

            float C  = 25.0f * ct, S = 25.0f * st;
            float U0 = -(x0 * C + yc * S);
            float V0 =  (x0 * S - yc * C);

            // fold per-pass tile offset into U0/V0
            float ox = ((float)(16 * (b - c)) + 0.5f) * 0.03125f;
            float oy = ((float)(16 * (a - r)) + 0.5f) * 0.03125f;
            float U0p = fmaf(ox, C, fmaf(oy, S, U0));
            float V0p = fmaf(oy, C, fmaf(-ox, S, V0));

            sA[e] = make_float4(C, S, U0p, V0p);
            sB[e] = make_float4(W, H, 0.125f * S, 0.125f * C);
            sC[e] = make_float4(p8[5], p8[6], p8[7], 0.f);
        }
    }
    __syncthreads();

    const int tot = sTot;
    const float gx = (float)tx * 0.03125f;
    const float gy = (float)ty * 0.03125f;

    float aR[4] = {0.f, 0.f, 0.f, 0.f};
    float aG[4] = {0.f, 0.f, 0.f, 0.f};
    float aB[4] = {0.f, 0.f, 0.f, 0.f};
    float T[4]  = {1.f, 1.f, 1.f, 1.f};

    // --- front-to-back blend, independent u/v per pixel ---
    for (int e = 0; e < tot; e++) {
        float4 A  = sA[e];
        float4 B  = sB[e];
        float4 Cc = sC[e];

        float u0 = fmaf(gx, A.x, fmaf(gy, A.y, A.z));
        float v0 = fmaf(gy, A.x, fmaf(-gx, A.y, A.w));

        #pragma unroll
        for (int k = 0; k < 4; k++) {
            float kf = (float)k;
            float u = fmaf(kf, B.z, u0);        // u0 + k*0.125*S (independent)
            float v = fmaf(kf, B.w, v0);
            float t1 = tanh_(B.x - fabsf(u));
            float t2 = tanh_(B.y - fabsf(v));
            float h1 = fmaf(t1, 0.5f, 0.5f);
            float h2 = fmaf(t2, 0.5f, 0.5f);
            float aT = h1 * h2 * T[k];          // alpha * transmittance
            aR[k] = fmaf(aT, Cc.x, aR[k]);
            aG[k] = fmaf(aT, Cc.y, aG[k]);
            aB[k] = fmaf(aT, Cc.z, aB[k]);
            T[k] -= aT;
        }
    }

    // --- late canvas read + composite ---
    const int x  = 16 * b + tx - 8;      // q = 8
    const int y0 = 16 * a + ty - 8;
    const bool vx = (unsigned)x < (unsigned)IMG;
    #pragma unroll
    for (int k = 0; k < 4; k++) {
        int y = y0 + 4 * k;
        if (vx && ((unsigned)y < (unsigned)IMG)) {
            int idx = y * IMG + x;
            out[idx]             = fmaf(canvas[idx],             T[k], aR[k]);
            out[PLANE + idx]     = fmaf(canvas[PLANE + idx],     T[k], aG[k]);
            out[2 * PLANE + idx] = fmaf(canvas[2 * PLANE + idx], T[k], aB[k]);
        }
    }
}

// ---------------------------------------------------------------------------
extern "C" void kernel_launch(void* const* d_in, const int* in_sizes, int n_in,
                              void* d_out, int out_size) {
    const float* param    = (const float*)d_in[0];   // (1,64,64,5,12) f32
    const int*   decision = (const int*)  d_in[1];   // (1,64,64,5)    i32
    const float* canvas   = (const float*)d_in[2];   // (1,3,1024,1024) f32
    float*       out      = (float*)d_out;           // (1,3,1024,1024) f32

    dim3 bs(16, 4);          // 64 threads, 4 px/thread
    dim3 gs(65, 65);         // padded 1040x1040 in 16x16 cells
    render_kernel<<<gs, bs>>>(param, decision, canvas, out);
}

// round 13
// speedup vs baseline: 1.1429x; 1.1429x over previous
#include <cuda_runtime.h>
#include <cuda_bf16.h>

// Problem constants: b=1, h=w=64, s=5, H=W=1024, ps=32, q=8
#define GRID_T   64
#define NTILES   (GRID_T * GRID_T)      // 4096
#define NSTROKE  5
#define IMG      1024
#define PLANE    (IMG * IMG)            // 1048576

__device__ __forceinline__ float tanh_(float x) {
    float r; asm("tanh.approx.f32 %0,%1;" : "=f"(r) : "f"(x)); return r;
}

// ---------------------------------------------------------------------------
// Single fused kernel. Block = one 16x16 padded-aligned cell, 64 threads
// (16x4), 4 pixels/thread (rows ty+{0,4,8,12}).
//
// Staging (warp 0, lanes 0..19, one per (pass,stroke)):
//   - decision (5x LDG) and param (2x LDG.128) issued together at entry so
//     their DRAM latencies overlap (R10 serialized them across a sync).
//   - per-pass counts exchanged via shfl (no intermediate __syncthreads).
//   - entries written to smem in REVERSED blend order => front-to-back.
// Render: front-to-back transmittance blend (identical to R10 inner loop);
// canvas read AFTER the loop: out = acc + canvas*T.
// ---------------------------------------------------------------------------
__global__ void __launch_bounds__(64)
render_kernel(const float* __restrict__ param,
              const int*   __restrict__ decision,
              const float* __restrict__ canvas,
              float*       __restrict__ out) {
    __shared__ float4 sA[4 * NSTROKE];   // (C, S, U0', V0')  [scaled by 25]
    __shared__ float4 sB[4 * NSTROKE];   // (W, H, dS, dC)    [scaled by 25]
    __shared__ float4 sC[4 * NSTROKE];   // (cr, cg, cb, -)
    __shared__ int    sTot;

    const int a = blockIdx.y;            // padded cell row: Y in [16a, 16a+16)
    const int b = blockIdx.x;
    const int tx  = threadIdx.x;         // 0..15
    const int ty  = threadIdx.y;         // 0..3
    const int tid = ty * 16 + tx;

    // --- warp-synchronous staging (warp 0, lanes 0..19) ---
    if (tid < 32) {
        const int lane = tid;
        const int PR[4] = {0, 1, 1, 0};
        const int PC[4] = {0, 1, 0, 1};
        int p = 0, i = 0, r = 0, c = 0, t = 0;
        bool valid = false;
        if (lane < 4 * NSTROKE) {
            p = lane / NSTROKE; i = lane - p * NSTROKE;
            r = (((a - 1) & 1) == PR[p]) ? (a - 1) : a;
            c = (((b - 1) & 1) == PC[p]) ? (b - 1) : b;
            valid = ((unsigned)r < 64u) && ((unsigned)c < 64u);
            t = r * GRID_T + c;
        }

        // issue BOTH loads immediately; latencies overlap
        int dec[NSTROKE];
        #pragma unroll
        for (int j = 0; j < NSTROKE; j++) dec[j] = 0;
        float4 q0 = make_float4(0.f, 0.f, 0.f, 0.f);
        float4 q1 = make_float4(0.f, 0.f, 0.f, 0.f);
        if (valid) {
            #pragma unroll
            for (int j = 0; j < NSTROKE; j++)
                dec[j] = decision[t * NSTROKE + j];
            const float4* q = (const float4*)(param + (size_t)(t * NSTROKE + i) * 12);
            q0 = q[0];                   // params 0..3
            q1 = q[1];                   // params 4..7
        }

        int cnt = 0;
        #pragma unroll
        for (int j = 0; j < NSTROKE; j++) cnt += (dec[j] != 0);

        const int c0 = __shfl_sync(0xffffffffu, cnt, 0);
        const int c1 = __shfl_sync(0xffffffffu, cnt, 5);
        const int c2 = __shfl_sync(0xffffffffu, cnt, 10);
        const int c3 = __shfl_sync(0xffffffffu, cnt, 15);
        const int tot = c0 + c1 + c2 + c3;
        if (lane == 0) sTot = tot;

        if (lane < 4 * NSTROKE && dec[i] != 0) {
            int pos = 0;
            #pragma unroll
            for (int j = 0; j < NSTROKE; j++) pos += (j < i) && (dec[j] != 0);
            int base = ((p > 0) ? c0 : 0) + ((p > 1) ? c1 : 0) + ((p > 2) ? c2 : 0);
            int e = tot - 1 - (base + pos);      // reversed => front-to-back

            float p8[8];
            p8[0] = __fdividef(1.0f, 1.0f + __expf(-q0.x));
            p8[1] = __fdividef(1.0f, 1.0f + __expf(-q0.y));
            p8[2] = __fdividef(1.0f, 1.0f + __expf(-q0.z));
            p8[3] = __fdividef(1.0f, 1.0f + __expf(-q0.w));
            p8[4] = __fdividef(1.0f, 1.0f + __expf(-q1.x));
            p8[5] = __fdividef(1.0f, 1.0f + __expf(-q1.y));
            p8[6] = __fdividef(1.0f, 1.0f + __expf(-q1.z));
            p8[7] = __fdividef(1.0f, 1.0f + __expf(-q1.w));

            float x0 = p8[0], yc = p8[1];
            float W = 12.5f * fmaxf(p8[2], 0.01f);   // 25 * (wd/2)
            float H = 12.5f * fmaxf(p8[3], 0.01f);
            float th = p8[4] * 3.14159265358979323846f;
            float st, ct;
            __sincosf(th, &st, &ct);

            float C  = 25.0f * ct, S = 25.0f * st;
            float U0 = -(x0 * C + yc * S);
            float V0 =  (x0 * S - yc * C);

            // fold per-pass tile offset into U0/V0
            float ox = ((float)(16 * (b - c)) + 0.5f) * 0.03125f;
            float oy = ((float)(16 * (a - r)) + 0.5f) * 0.03125f;
            float U0p = fmaf(ox, C, fmaf(oy, S, U0));
            float V0p = fmaf(oy, C, fmaf(-ox, S, V0));

            sA[e] = make_float4(C, S, U0p, V0p);
            sB[e] = make_float4(W, H, 0.125f * S, 0.125f * C);
            sC[e] = make_float4(p8[5], p8[6], p8[7], 0.f);
        }
    }
    __syncthreads();

    const int tot = sTot;
    const float gx = (float)tx * 0.03125f;
    const float gy = (float)ty * 0.03125f;

    float aR[4] = {0.f, 0.f, 0.f, 0.f};
    float aG[4] = {0.f, 0.f, 0.f, 0.f};
    float aB[4] = {0.f, 0.f, 0.f, 0.f};
    float T[4]  = {1.f, 1.f, 1.f, 1.f};

    // --- front-to-back blend (R10 inner loop, serial u/v increments) ---
    for (int e = 0; e < tot; e++) {
        float4 A  = sA[e];
        float4 B  = sB[e];
        float4 Cc = sC[e];

        float u = fmaf(gx, A.x, fmaf(gy, A.y, A.z));
        float v = fmaf(gy, A.x, fmaf(-gx, A.y, A.w));

        #pragma unroll
        for (int k = 0; k < 4; k++) {
            float t1 = tanh_(B.x - fabsf(u));
            float t2 = tanh_(B.y - fabsf(v));
            float h1 = fmaf(t1, 0.5f, 0.5f);
            float h2 = fmaf(t2, 0.5f, 0.5f);
            float aT = h1 * h2 * T[k];          // alpha * transmittance
            aR[k] = fmaf(aT, Cc.x, aR[k]);
            aG[k] = fmaf(aT, Cc.y, aG[k]);
            aB[k] = fmaf(aT, Cc.z, aB[k]);
            T[k] -= aT;
            u += B.z;                           // +4 rows: du = 0.125*S
            v += B.w;                           //          dv = 0.125*C
        }
    }

    // --- late canvas read + composite ---
    const int x  = 16 * b + tx - 8;      // q = 8
    const int y0 = 16 * a + ty - 8;
    const bool vx = (unsigned)x < (unsigned)IMG;
    #pragma unroll
    for (int k = 0; k < 4; k++) {
        int y = y0 + 4 * k;
        if (vx && ((unsigned)y < (unsigned)IMG)) {
            int idx = y * IMG + x;
            out[idx]             = fmaf(canvas[idx],             T[k], aR[k]);
            out[PLANE + idx]     = fmaf(canvas[PLANE + idx],     T[k], aG[k]);
            out[2 * PLANE + idx] = fmaf(canvas[2 * PLANE + idx], T[k], aB[k]);
        }
    }
}

// ---------------------------------------------------------------------------
extern "C" void kernel_launch(void* const* d_in, const int* in_sizes, int n_in,
                              void* d_out, int out_size) {
    const float* param    = (const float*)d_in[0];   // (1,64,64,5,12) f32
    const int*   decision = (const int*)  d_in[1];   // (1,64,64,5)    i32
    const float* canvas   = (const float*)d_in[2];   // (1,3,1024,1024) f32
    float*       out      = (float*)d_out;           // (1,3,1024,1024) f32

    dim3 bs(16, 4);          // 64 threads, 4 px/thread
    dim3 gs(65, 65);         // padded 1040x1040 in 16x16 cells
    render_kernel<<<gs, bs>>>(param, decision, canvas, out);
}

// round 14
// speedup vs baseline: 1.1654x; 1.0197x over previous
#include <cuda_runtime.h>
#include <cuda_bf16.h>

// Problem constants: b=1, h=w=64, s=5, H=W=1024, ps=32, q=8
#define GRID_T   64
#define NTILES   (GRID_T * GRID_T)      // 4096
#define NSTROKE  5
#define IMG      1024
#define PLANE    (IMG * IMG)            // 1048576

typedef unsigned long long u64;

__device__ __forceinline__ float tanh_(float x) {
    float r; asm("tanh.approx.f32 %0,%1;" : "=f"(r) : "f"(x)); return r;
}
__device__ __forceinline__ u64 pk2(float lo, float hi) {
    u64 r; asm("mov.b64 %0,{%1,%2};" : "=l"(r) : "f"(lo), "f"(hi)); return r;
}
__device__ __forceinline__ void upk2(u64 v, float& lo, float& hi) {
    asm("mov.b64 {%0,%1},%2;" : "=f"(lo), "=f"(hi) : "l"(v));
}
__device__ __forceinline__ u64 fma2_(u64 a, u64 b, u64 c) {
    u64 r; asm("fma.rn.f32x2 %0,%1,%2,%3;" : "=l"(r) : "l"(a), "l"(b), "l"(c)); return r;
}
__device__ __forceinline__ u64 add2_(u64 a, u64 b) {
    u64 r; asm("add.rn.f32x2 %0,%1,%2;" : "=l"(r) : "l"(a), "l"(b)); return r;
}
__device__ __forceinline__ u64 mul2_(u64 a, u64 b) {
    u64 r; asm("mul.rn.f32x2 %0,%1,%2;" : "=l"(r) : "l"(a), "l"(b)); return r;
}
__device__ __forceinline__ u64 and2_(u64 a, u64 m) {
    u64 r; asm("and.b64 %0,%1,%2;" : "=l"(r) : "l"(a), "l"(m)); return r;
}

// ---------------------------------------------------------------------------
// Single fused kernel (R10 staging + packed f32x2 render).
// Block = one 16x16 padded-aligned cell, 64 threads (16x4), 4 px/thread
// (rows ty+{0,4,8,12}) processed as TWO independent f32x2 pairs.
// Front-to-back blend; canvas read after the loop.
// ---------------------------------------------------------------------------
__global__ void __launch_bounds__(64)
render_kernel(const float* __restrict__ param,
              const int*   __restrict__ decision,
              const float* __restrict__ canvas,
              float*       __restrict__ out) {
    __shared__ float4 sA[4 * NSTROKE];   // (C, S, U0', V0')  [scaled by 25]
    __shared__ float4 sB[4 * NSTROKE];   // (W, H, dS, dC)    [scaled by 25]
    __shared__ float4 sC[4 * NSTROKE];   // (cr, cg, cb, -)
    __shared__ int    sCnt[4];

    const int a = blockIdx.y;            // padded cell row: Y in [16a, 16a+16)
    const int b = blockIdx.x;
    const int tx  = threadIdx.x;         // 0..15
    const int ty  = threadIdx.y;         // 0..3
    const int tid = ty * 16 + tx;

    // --- staging (R10 verbatim: two-phase, smem counts) ---
    const int PR[4] = {0, 1, 1, 0};
    const int PC[4] = {0, 1, 0, 1};
    int p = 0, i = 0, r = 0, c = 0, t = 0;
    bool valid = false;
    if (tid < 4 * NSTROKE) {
        p = tid / NSTROKE; i = tid - p * NSTROKE;
        r = (((a - 1) & 1) == PR[p]) ? (a - 1) : a;
        c = (((b - 1) & 1) == PC[p]) ? (b - 1) : b;
        valid = ((unsigned)r < 64u) && ((unsigned)c < 64u);
        t = r * GRID_T + c;
    }

    int dec[NSTROKE];
    if (tid < 4 * NSTROKE && valid) {
        #pragma unroll
        for (int j = 0; j < NSTROKE; j++) dec[j] = decision[t * NSTROKE + j];
    } else {
        #pragma unroll
        for (int j = 0; j < NSTROKE; j++) dec[j] = 0;
    }
    if (tid < 4 * NSTROKE && i == 0) {
        int cnt = 0;
        #pragma unroll
        for (int j = 0; j < NSTROKE; j++) cnt += (dec[j] != 0);
        sCnt[p] = cnt;
    }
    __syncthreads();

    const int cnt0 = sCnt[0], cnt1 = sCnt[1], cnt2 = sCnt[2], cnt3 = sCnt[3];
    const int tot  = cnt0 + cnt1 + cnt2 + cnt3;

    if (tid < 4 * NSTROKE && dec[i] != 0) {
        int pos = 0;
        #pragma unroll
        for (int j = 0; j < NSTROKE; j++) pos += (j < i) && (dec[j] != 0);
        int base = ((p > 0) ? cnt0 : 0) + ((p > 1) ? cnt1 : 0) + ((p > 2) ? cnt2 : 0);
        int e = tot - 1 - (base + pos);          // reversed => front-to-back

        const float* q = param + (size_t)(t * NSTROKE + i) * 12;
        float p8[8];
        #pragma unroll
        for (int k = 0; k < 8; k++)
            p8[k] = __fdividef(1.0f, 1.0f + __expf(-q[k]));   // jax.nn.sigmoid

        float x0 = p8[0], yc = p8[1];
        float W = 12.5f * fmaxf(p8[2], 0.01f);   // 25 * (wd/2)
        float H = 12.5f * fmaxf(p8[3], 0.01f);
        float th = p8[4] * 3.14159265358979323846f;
        float st, ct;
        __sincosf(th, &st, &ct);

        float C  = 25.0f * ct, S = 25.0f * st;
        float U0 = -(x0 * C + yc * S);
        float V0 =  (x0 * S - yc * C);

        float ox = ((float)(16 * (b - c)) + 0.5f) * 0.03125f;
        float oy = ((float)(16 * (a - r)) + 0.5f) * 0.03125f;
        float U0p = fmaf(ox, C, fmaf(oy, S, U0));
        float V0p = fmaf(oy, C, fmaf(-ox, S, V0));

        sA[e] = make_float4(C, S, U0p, V0p);
        sB[e] = make_float4(W, H, 0.125f * S, 0.125f * C);
        sC[e] = make_float4(p8[5], p8[6], p8[7], 0.f);
    }
    __syncthreads();

    // --- packed f32x2 render: 2 pairs = rows (k0,k1)=(0,4px), (k2,k3)=(8,12px)
    const float gx = (float)tx * 0.03125f;
    const float gy = (float)ty * 0.03125f;

    const u64 MASK = 0x7FFFFFFF7FFFFFFFULL;      // clear both sign bits
    const u64 NEG1 = pk2(-1.f, -1.f);
    const u64 HALF = pk2(0.5f, 0.5f);

    u64 aR0 = 0, aG0 = 0, aB0 = 0, T0 = pk2(1.f, 1.f);   // pair A (rows 0,4)
    u64 aR1 = 0, aG1 = 0, aB1 = 0, T1 = pk2(1.f, 1.f);   // pair B (rows 8,12)

    for (int e = 0; e < tot; e++) {              // front-to-back
        float4 A  = sA[e];
        float4 B  = sB[e];
        float4 Cc = sC[e];

        float u0 = fmaf(gx, A.x, fmaf(gy, A.y, A.z));
        float v0 = fmaf(gy, A.x, fmaf(-gx, A.y, A.w));
        float u1 = u0 + B.z;                     // +4 rows
        float v1 = v0 + B.w;
        u64 uA = pk2(u0, u1), vA = pk2(v0, v1);
        float ds2 = B.z + B.z, dc2 = B.w + B.w;  // +8 rows
        u64 uB = add2_(uA, pk2(ds2, ds2));
        u64 vB = add2_(vA, pk2(dc2, dc2));

        u64 W2  = pk2(B.x, B.x), H2 = pk2(B.y, B.y);
        u64 CR2 = pk2(Cc.x, Cc.x);
        u64 CG2 = pk2(Cc.y, Cc.y);
        u64 CB2 = pk2(Cc.z, Cc.z);

        // ---- pair A ----
        {
            u64 zu = fma2_(and2_(uA, MASK), NEG1, W2);   // W - |u|
            u64 zv = fma2_(and2_(vA, MASK), NEG1, H2);
            float z0, z1, z2, z3;
            upk2(zu, z0, z1); upk2(zv, z2, z3);
            u64 tu = pk2(tanh_(z0), tanh_(z1));
            u64 tv = pk2(tanh_(z2), tanh_(z3));
            u64 hu = fma2_(tu, HALF, HALF);
            u64 hv = fma2_(tv, HALF, HALF);
            u64 aT = mul2_(mul2_(hu, hv), T0);           // alpha * T
            aR0 = fma2_(aT, CR2, aR0);
            aG0 = fma2_(aT, CG2, aG0);
            aB0 = fma2_(aT, CB2, aB0);
            T0  = fma2_(aT, NEG1, T0);
        }
        // ---- pair B ----
        {
            u64 zu = fma2_(and2_(uB, MASK), NEG1, W2);
            u64 zv = fma2_(and2_(vB, MASK), NEG1, H2);
            float z0, z1, z2, z3;
            upk2(zu, z0, z1); upk2(zv, z2, z3);
            u64 tu = pk2(tanh_(z0), tanh_(z1));
            u64 tv = pk2(tanh_(z2), tanh_(z3));
            u64 hu = fma2_(tu, HALF, HALF);
            u64 hv = fma2_(tv, HALF, HALF);
            u64 aT = mul2_(mul2_(hu, hv), T1);
            aR1 = fma2_(aT, CR2, aR1);
            aG1 = fma2_(aT, CG2, aG1);
            aB1 = fma2_(aT, CB2, aB1);
            T1  = fma2_(aT, NEG1, T1);
        }
    }

    // --- late canvas read + composite ---
    float rr[4], gg[4], bb[4], TT[4];
    upk2(aR0, rr[0], rr[1]); upk2(aR1, rr[2], rr[3]);
    upk2(aG0, gg[0], gg[1]); upk2(aG1, gg[2], gg[3]);
    upk2(aB0, bb[0], bb[1]); upk2(aB1, bb[2], bb[3]);
    upk2(T0,  TT[0], TT[1]); upk2(T1,  TT[2], TT[3]);

    const int x  = 16 * b + tx - 8;      // q = 8
    const int y0 = 16 * a + ty - 8;
    const bool vx = (unsigned)x < (unsigned)IMG;
    #pragma unroll
    for (int k = 0; k < 4; k++) {
        int y = y0 + 4 * k;
        if (vx && ((unsigned)y < (unsigned)IMG)) {
            int idx = y * IMG + x;
            out[idx]             = fmaf(canvas[idx],             TT[k], rr[k]);
            out[PLANE + idx]     = fmaf(canvas[PLANE + idx],     TT[k], gg[k]);
            out[2 * PLANE + idx] = fmaf(canvas[2 * PLANE + idx], TT[k], bb[k]);
        }
    }
}

// ---------------------------------------------------------------------------
extern "C" void kernel_launch(void* const* d_in, const int* in_sizes, int n_in,
                              void* d_out, int out_size) {
    const float* param    = (const float*)d_in[0];   // (1,64,64,5,12) f32
    const int*   decision = (const int*)  d_in[1];   // (1,64,64,5)    i32
    const float* canvas   = (const float*)d_in[2];   // (1,3,1024,1024) f32
    float*       out      = (float*)d_out;           // (1,3,1024,1024) f32

    dim3 bs(16, 4);          // 64 threads, 4 px/thread (2 f32x2 pairs)
    dim3 gs(65, 65);         // padded 1040x1040 in 16x16 cells
    render_kernel<<<gs, bs>>>(param, decision, canvas, out);
}

// round 15
// speedup vs baseline: 1.2786x; 1.0972x over previous
#include <cuda_runtime.h>
#include <cuda_bf16.h>

// Problem constants: b=1, h=w=64, s=5, H=W=1024, ps=32, q=8
#define GRID_T   64
#define NSTROKE  5
#define IMG      1024
#define PLANE    (IMG * IMG)            // 1048576

__device__ __forceinline__ float tanh_(float x) {
    float r; asm("tanh.approx.f32 %0,%1;" : "=f"(r) : "f"(x)); return r;
}

// ---------------------------------------------------------------------------
// Single fused kernel. Block = 2x2 padded 16x16 cells (32x32 px), 256 threads,
// 4 px/thread (rows ty+{0,4,8,12}).
//
// KEY CHANGE vs R10: stroke constants are folded to the TILE origin (not the
// cell), so u,v are evaluated in GLOBAL pixel coords:
//     u = Gx*C + Gy*S + U0''   with U0'' = U0 - 0.5*(c*C + r*S)
//     v = Gy*C - Gx*S + V0''   with V0'' = V0 + 0.5*(c*S - r*C)
// => prepped entries are cell-independent, so ONE staging pass covers the
// 3x3 tiles used by all 4 cells (45 preps / 4 cells vs 20 / cell before).
//
// Staging: threads 0..44, one per (tile, stroke); single phase, one sync.
// Render: cell = tid>>6 (warp-uniform). Front-to-back blend: pass p=3..0,
// strokes i=cnt-1..0, reading per-tile smem entries (LDS broadcast).
// Canvas read after the loop: out = acc + canvas*T.
// ---------------------------------------------------------------------------
__global__ void __launch_bounds__(256)
render_kernel(const float* __restrict__ param,
              const int*   __restrict__ decision,
              const float* __restrict__ canvas,
              float*       __restrict__ out) {
    __shared__ float4 sA[9][NSTROKE];    // (C, S, U0'', V0'')  [scaled by 25]
    __shared__ float4 sB[9][NSTROKE];    // (W, H, dS, dC)      [scaled by 25]
    __shared__ float4 sC[9][NSTROKE];    // (cr, cg, cb, -)
    __shared__ int    sCnt[9];

    const int r0 = 2 * blockIdx.y - 1;   // tile row of local tile (0,*)
    const int c0 = 2 * blockIdx.x - 1;   // tile col of local tile (*,0)
    const int tid = threadIdx.x;

    // --- staging: one thread per (tile, stroke), tiles = 3x3 around block ---
    if (tid < 9 * NSTROKE) {
        const int lt = tid / NSTROKE;    // local tile 0..8
        const int i  = tid - lt * NSTROKE;
        const int r  = r0 + lt / 3;
        const int c  = c0 + lt % 3;
        const bool valid = ((unsigned)r < 64u) && ((unsigned)c < 64u);
        const int t = r * GRID_T + c;

        int dec[NSTROKE];
        #pragma unroll
        for (int j = 0; j < NSTROKE; j++)
            dec[j] = valid ? decision[t * NSTROKE + j] : 0;

        int cnt = 0;
        #pragma unroll
        for (int j = 0; j < NSTROKE; j++) cnt += (dec[j] != 0);
        if (i == 0) sCnt[lt] = cnt;

        if (dec[i] != 0) {
            int pos = 0;
            #pragma unroll
            for (int j = 0; j < NSTROKE; j++) pos += (j < i) && (dec[j] != 0);

            const float* q = param + (size_t)(t * NSTROKE + i) * 12;
            float p8[8];
            #pragma unroll
            for (int k = 0; k < 8; k++)
                p8[k] = __fdividef(1.0f, 1.0f + __expf(-q[k]));  // sigmoid

            float x0 = p8[0], yc = p8[1];
            float W = 12.5f * fmaxf(p8[2], 0.01f);   // 25 * (wd/2)
            float H = 12.5f * fmaxf(p8[3], 0.01f);
            float th = p8[4] * 3.14159265358979323846f;
            float st, ct;
            __sincosf(th, &st, &ct);

            float C  = 25.0f * ct, S = 25.0f * st;
            float U0 = -(x0 * C + yc * S);
            float V0 =  (x0 * S - yc * C);

            // fold TILE origin (16r,16c padded px = 0.5r,0.5c tile units)
            float fc = 0.5f * (float)c, fr = 0.5f * (float)r;
            float U0p = U0 - (fc * C + fr * S);
            float V0p = V0 + (fc * S - fr * C);

            sA[lt][pos] = make_float4(C, S, U0p, V0p);
            sB[lt][pos] = make_float4(W, H, 0.125f * S, 0.125f * C);
            sC[lt][pos] = make_float4(p8[5], p8[6], p8[7], 0.f);
        }
    }
    __syncthreads();

    // --- render: cell = tid>>6 (warp-uniform); 4 px/thread ---
    const int cl = tid >> 6;             // 0..3
    const int t6 = tid & 63;
    const int tx = t6 & 15;
    const int ty = t6 >> 4;              // 0..3
    const int a  = 2 * blockIdx.y + (cl >> 1);   // padded cell row
    const int bb = 2 * blockIdx.x + (cl & 1);    // padded cell col

    const int Xp  = 16 * bb + tx;        // padded pixel coords
    const int Yp0 = 16 * a + ty;
    const float Gx = ((float)Xp  + 0.5f) * 0.03125f;   // global tile units
    const float Gy = ((float)Yp0 + 0.5f) * 0.03125f;

    float aR[4] = {0.f, 0.f, 0.f, 0.f};
    float aG[4] = {0.f, 0.f, 0.f, 0.f};
    float aB[4] = {0.f, 0.f, 0.f, 0.f};
    float T[4]  = {1.f, 1.f, 1.f, 1.f};

    const int PR[4] = {0, 1, 1, 0};
    const int PC[4] = {0, 1, 0, 1};

    #pragma unroll
    for (int p = 3; p >= 0; --p) {       // reversed passes => front-to-back
        int r = (((a - 1) & 1) == PR[p]) ? (a - 1) : a;
        int c = (((bb - 1) & 1) == PC[p]) ? (bb - 1) : bb;
        int lt = (r - r0) * 3 + (c - c0);
        int cn = sCnt[lt];

        for (int i = cn - 1; i >= 0; --i) {      // reversed strokes
            float4 A  = sA[lt][i];
            float4 B  = sB[lt][i];
            float4 Cc = sC[lt][i];

            float u = fmaf(Gx, A.x, fmaf(Gy, A.y, A.z));
            float v = fmaf(Gy, A.x, fmaf(-Gx, A.y, A.w));

            #pragma unroll
            for (int k = 0; k < 4; k++) {
                float t1 = tanh_(B.x - fabsf(u));
                float t2 = tanh_(B.y - fabsf(v));
                float h1 = fmaf(t1, 0.5f, 0.5f);
                float h2 = fmaf(t2, 0.5f, 0.5f);
                float aT = h1 * h2 * T[k];       // alpha * transmittance
                aR[k] = fmaf(aT, Cc.x, aR[k]);
                aG[k] = fmaf(aT, Cc.y, aG[k]);
                aB[k] = fmaf(aT, Cc.z, aB[k]);
                T[k] -= aT;
                u += B.z;                        // +4 rows: du = 0.125*S
                v += B.w;                        //          dv = 0.125*C
            }
        }
    }

    // --- late canvas read + composite ---
    const int x  = Xp - 8;               // q = 8
    const int y0 = Yp0 - 8;
    const bool vx = (unsigned)x < (unsigned)IMG;
    #pragma unroll
    for (int k = 0; k < 4; k++) {
        int y = y0 + 4 * k;
        if (vx && ((unsigned)y < (unsigned)IMG)) {
            int idx = y * IMG + x;
            out[idx]             = fmaf(canvas[idx],             T[k], aR[k]);
            out[PLANE + idx]     = fmaf(canvas[PLANE + idx],     T[k], aG[k]);
            out[2 * PLANE + idx] = fmaf(canvas[2 * PLANE + idx], T[k], aB[k]);
        }
    }
}

// ---------------------------------------------------------------------------
extern "C" void kernel_launch(void* const* d_in, const int* in_sizes, int n_in,
                              void* d_out, int out_size) {
    const float* param    = (const float*)d_in[0];   // (1,64,64,5,12) f32
    const int*   decision = (const int*)  d_in[1];   // (1,64,64,5)    i32
    const float* canvas   = (const float*)d_in[2];   // (1,3,1024,1024) f32
    float*       out      = (float*)d_out;           // (1,3,1024,1024) f32

    dim3 bs(256);            // 2x2 cells per block, 4 px/thread
    dim3 gs(33, 33);         // 66x66 cells (index 65 auto-invalid)
    render_kernel<<<gs, bs>>>(param, decision, canvas, out);
}